// round 15
// baseline (speedup 1.0000x reference)
#include <cuda_runtime.h>
#include <cuda_fp16.h>

// Problem constants
#define Bn   64
#define Rn   4608
#define Cn   32
#define INn  8
#define OUTn 16
#define RCHUNK 64
#define NCHUNK 72    // Rn / RCHUNK

// Scratch (device globals; allocation-free per harness rules)
static __device__ float g_xM[(size_t)Rn * INn * Bn];                // x as [r][i][b] (9.4 MB, L2-hot)
static __device__ float g_red[(size_t)Cn * NCHUNK * Bn * 17];       // pass partials (n[16], d)
static __device__ float g_v1[(size_t)Bn * Cn * OUTn];
static __device__ float g_vcur[(size_t)Bn * Cn * OUTn];             // current logit vector

// ---- tf32 / mma helpers (fragment mapping validated in R14: rel_err matched) ----
__device__ __forceinline__ unsigned tf32(float f) {
    unsigned r;
    asm("cvt.rna.tf32.f32 %0, %1;" : "=r"(r) : "f"(f));
    return r;
}

__device__ __forceinline__ void mma8_zero(
    float& d0, float& d1, float& d2, float& d3,
    unsigned a0, unsigned a1, unsigned a2, unsigned a3,
    unsigned b0, unsigned b1)
{
    float z = 0.f;
    asm("mma.sync.aligned.m16n8k8.row.col.f32.tf32.tf32.f32 "
        "{%0,%1,%2,%3},{%4,%5,%6,%7},{%8,%9},{%10,%10,%10,%10};"
        : "=f"(d0), "=f"(d1), "=f"(d2), "=f"(d3)
        : "r"(a0), "r"(a1), "r"(a2), "r"(a3), "r"(b0), "r"(b1), "f"(z));
}

__device__ __forceinline__ void mma8_acc(
    float& d0, float& d1, float& d2, float& d3,
    unsigned a0, unsigned a1, unsigned a2, unsigned a3,
    unsigned b0, unsigned b1)
{
    asm("mma.sync.aligned.m16n8k8.row.col.f32.tf32.tf32.f32 "
        "{%0,%1,%2,%3},{%4,%5,%6,%7},{%8,%9},{%0,%1,%2,%3};"
        : "+f"(d0), "+f"(d1), "+f"(d2), "+f"(d3)
        : "r"(a0), "r"(a1), "r"(a2), "r"(a3), "r"(b0), "r"(b1));
}

// ============================================================================
// k0: transpose x (64 b, 9216 float4-cols) -> xM[r][i][b] scalar floats.
// ============================================================================
__global__ void __launch_bounds__(256)
k0_transpose(const float4* __restrict__ x4) {
    __shared__ float4 tile[32][33];
    const int f0 = blockIdx.x * 32;
    const int b0 = blockIdx.y * 32;
    const int tx = threadIdx.x;
    const int ty0 = threadIdx.y;
    #pragma unroll
    for (int j = 0; j < 4; j++) {
        int ty = ty0 * 4 + j;
        tile[ty][tx] = x4[(size_t)(b0 + ty) * (Rn * 2) + f0 + tx];
    }
    __syncthreads();
    #pragma unroll
    for (int j = 0; j < 4; j++) {
        int ty = ty0 * 4 + j;
        float4 v = tile[tx][ty];           // = x4[b0+tx][f0+ty]
        int f = f0 + ty;                   // f = r*2 + h
        size_t base = ((size_t)(f >> 1) * 8 + (f & 1) * 4) * Bn + b0 + tx;
        g_xM[base]          = v.x;
        g_xM[base + Bn]     = v.y;
        g_xM[base + 2 * Bn] = v.z;
        g_xM[base + 3 * Bn] = v.w;
    }
}

// ============================================================================
// kpass: ONE fused routing pass — u recomputed via tf32 mma, NEVER stored.
// Grid (Cn, NCHUNK), block 256 = 8 warps; warp covers 8 r, each r is a
// 64x8 @ 8x16 GEMM (4 m-tiles x 2 n-tiles of m16n8k8).
// mode 0: e = 1 -> pure accumulating mma (iteration-1 sums).
// mode 1: mma -> logits (smem v) -> shfl-reduced -> deduped exp -> second
//         mma regenerates u for the e*u accumulation (caps register peak).
// All reductions fixed-order -> deterministic.
// ============================================================================
__global__ void __launch_bounds__(256)
kpass(int mode, const float* __restrict__ w) {
    const int c     = blockIdx.x;
    const int chunk = blockIdx.y;
    const int r0    = chunk * RCHUNK;
    const int tid   = threadIdx.x;
    const int warp  = tid >> 5;
    const int lane  = tid & 31;
    const int g     = lane >> 2;       // groupID 0..7
    const int t4    = lane & 3;        // thread-in-group 0..3

    __shared__ float sW[RCHUNK * 128];   // 32 KB tf32 W; reused for n-reduction
    __shared__ float sV[Bn * 18];        // padded v (bank-conflict-free)
    __shared__ float sD[8][Bn];          // per-warp d partials

    // Stage W chunk, tf32-rounded once (coalesced float4)
    {
        const float4* wg = reinterpret_cast<const float4*>(w);
        float4*       ws = reinterpret_cast<float4*>(sW);
        for (int t = tid; t < RCHUNK * 32; t += 256) {
            int rr = t >> 5;
            int q  = t & 31;
            float4 v = wg[((size_t)(r0 + rr) * Cn + c) * 32 + q];
            v.x = __uint_as_float(tf32(v.x));
            v.y = __uint_as_float(tf32(v.y));
            v.z = __uint_as_float(tf32(v.z));
            v.w = __uint_as_float(tf32(v.w));
            ws[rr * 32 + q] = v;
        }
    }
    if (mode) {
        for (int t = tid; t < Bn * OUTn; t += 256) {
            int b_ = t >> 4, o_ = t & 15;
            sV[b_ * 18 + o_] = g_vcur[((size_t)b_ * Cn + c) * OUTn + o_];
        }
    }
    __syncthreads();

    float dacc[4][2][4];               // n accumulators (mma fragment layout)
    #pragma unroll
    for (int mi = 0; mi < 4; mi++)
        #pragma unroll
        for (int ni = 0; ni < 2; ni++)
            #pragma unroll
            for (int q = 0; q < 4; q++) dacc[mi][ni][q] = 0.f;
    float dsum[8];
    #pragma unroll
    for (int j = 0; j < 8; j++) dsum[j] = 0.f;

    for (int k = 0; k < 8; k++) {
        const int rr = warp * 8 + k;
        const int r  = r0 + rr;

        // A fragments: x[r][i][b] (L2-hot, sector-coalesced)
        const float* xr = g_xM + (size_t)r * (INn * Bn);
        unsigned A[4][4];
        #pragma unroll
        for (int mi = 0; mi < 4; mi++) {
            int bb = mi * 16 + g;
            A[mi][0] = tf32(xr[t4 * Bn + bb]);
            A[mi][1] = tf32(xr[t4 * Bn + bb + 8]);
            A[mi][2] = tf32(xr[(t4 + 4) * Bn + bb]);
            A[mi][3] = tf32(xr[(t4 + 4) * Bn + bb + 8]);
        }
        // B fragments from staged W
        const float* wrow = sW + rr * 128;
        unsigned B[2][2];
        #pragma unroll
        for (int ni = 0; ni < 2; ni++) {
            B[ni][0] = __float_as_uint(wrow[t4 * 16 + ni * 8 + g]);
            B[ni][1] = __float_as_uint(wrow[(t4 + 4) * 16 + ni * 8 + g]);
        }

        if (mode == 0) {
            // iteration 1: plain sum of u over r — accumulate directly
            #pragma unroll
            for (int mi = 0; mi < 4; mi++)
                #pragma unroll
                for (int ni = 0; ni < 2; ni++)
                    mma8_acc(dacc[mi][ni][0], dacc[mi][ni][1],
                             dacc[mi][ni][2], dacc[mi][ni][3],
                             A[mi][0], A[mi][1], A[mi][2], A[mi][3],
                             B[ni][0], B[ni][1]);
        } else {
            // Phase A: u -> logit partials (u transient, freed per tile)
            float pb[8];
            #pragma unroll
            for (int j = 0; j < 8; j++) pb[j] = 0.f;
            #pragma unroll
            for (int mi = 0; mi < 4; mi++) {
                int bb = mi * 16 + g;
                #pragma unroll
                for (int ni = 0; ni < 2; ni++) {
                    float u0, u1, u2, u3;
                    mma8_zero(u0, u1, u2, u3,
                              A[mi][0], A[mi][1], A[mi][2], A[mi][3],
                              B[ni][0], B[ni][1]);
                    int o = ni * 8 + 2 * t4;
                    float2 vb  = *reinterpret_cast<const float2*>(&sV[bb * 18 + o]);
                    float2 vb8 = *reinterpret_cast<const float2*>(&sV[(bb + 8) * 18 + o]);
                    pb[2 * mi]     = fmaf(u0, vb.x,  fmaf(u1, vb.y,  pb[2 * mi]));
                    pb[2 * mi + 1] = fmaf(u2, vb8.x, fmaf(u3, vb8.y, pb[2 * mi + 1]));
                }
            }
            // Phase B: full logits (reduce over t4), deduped exp + broadcast
            #pragma unroll
            for (int j = 0; j < 8; j++) {
                pb[j] += __shfl_xor_sync(0xffffffffu, pb[j], 1);
                pb[j] += __shfl_xor_sync(0xffffffffu, pb[j], 2);
            }
            float e0 = __expf(pb[2 * t4]);       // logits bounded; no max-sub
            float e1 = __expf(pb[2 * t4 + 1]);
            float e[8];
            #pragma unroll
            for (int j = 0; j < 8; j++)
                e[j] = __shfl_sync(0xffffffffu, (j & 1) ? e1 : e0,
                                   (lane & ~3) | (j >> 1));
            // Phase C: regenerate u, accumulate e*u and d
            #pragma unroll
            for (int mi = 0; mi < 4; mi++) {
                #pragma unroll
                for (int ni = 0; ni < 2; ni++) {
                    float u0, u1, u2, u3;
                    mma8_zero(u0, u1, u2, u3,
                              A[mi][0], A[mi][1], A[mi][2], A[mi][3],
                              B[ni][0], B[ni][1]);
                    dacc[mi][ni][0] = fmaf(e[2 * mi],     u0, dacc[mi][ni][0]);
                    dacc[mi][ni][1] = fmaf(e[2 * mi],     u1, dacc[mi][ni][1]);
                    dacc[mi][ni][2] = fmaf(e[2 * mi + 1], u2, dacc[mi][ni][2]);
                    dacc[mi][ni][3] = fmaf(e[2 * mi + 1], u3, dacc[mi][ni][3]);
                }
            }
            #pragma unroll
            for (int j = 0; j < 8; j++) dsum[j] += e[j];
        }
    }

    // ---- reduce (n, d) across the 8 warps (fixed order) ----
    __syncthreads();                    // done with sW contents
    float* sred = sW;                   // [8 warp][64 b][16 o] = 32 KB exactly
    #pragma unroll
    for (int mi = 0; mi < 4; mi++) {
        #pragma unroll
        for (int ni = 0; ni < 2; ni++) {
            int bb = mi * 16 + g;
            int oo = ni * 8 + 2 * t4;
            float* p = sred + ((size_t)warp * Bn + bb) * OUTn + oo;
            p[0]   = dacc[mi][ni][0];
            p[1]   = dacc[mi][ni][1];
            p[128] = dacc[mi][ni][2];   // b+8 -> +8*16 floats
            p[129] = dacc[mi][ni][3];
        }
    }
    if (t4 == 0) {
        #pragma unroll
        for (int j = 0; j < 8; j++)
            sD[warp][(j >> 1) * 16 + (j & 1) * 8 + g] = dsum[j];
    }
    __syncthreads();
    #pragma unroll
    for (int s = 0; s < 4; s++) {
        int idx = tid * 4 + s;
        int b_ = idx >> 4, o_ = idx & 15;
        float acc = 0.f;
        #pragma unroll
        for (int wg_ = 0; wg_ < 8; wg_++)
            acc += sred[((size_t)wg_ * Bn + b_) * OUTn + o_];
        g_red[(((size_t)c * NCHUNK + chunk) * Bn + b_) * 17 + o_] = acc;
    }
    if (tid < Bn) {
        float acc = 0.f;
        #pragma unroll
        for (int wg_ = 0; wg_ < 8; wg_++) acc += sD[wg_][tid];
        g_red[(((size_t)c * NCHUNK + chunk) * Bn + tid) * 17 + 16] = acc;
    }
}

// ============================================================================
// kf_v1: v1 = squash(mean_r u_r) from pass-0 partials; seeds g_vcur = v1.
// ============================================================================
__global__ void __launch_bounds__(32)
kf_v1() {
    const int bc = blockIdx.x;
    const int b  = bc >> 5;
    const int c  = bc & 31;
    const int t  = threadIdx.x;

    float acc = 0.f;
    if (t < OUTn) {
        for (int ch = 0; ch < NCHUNK; ch++)
            acc += g_red[(((size_t)c * NCHUNK + ch) * Bn + b) * 17 + t];
    }
    float val = (t < OUTn) ? acc * (1.0f / Rn) : 0.f;
    float sq = val * val;
    #pragma unroll
    for (int off = 16; off; off >>= 1) sq += __shfl_xor_sync(0xffffffffu, sq, off);
    float coef = (sq / (1.f + sq)) * rsqrtf(sq + 1e-8f);
    float v = val * coef;
    if (t < OUTn) {
        g_v1[(size_t)bc * OUTn + t]   = v;
        g_vcur[(size_t)bc * OUTn + t] = v;
    }
}

// ============================================================================
// kf_fin: reduce chunk partials -> softmax-weighted sum -> squash.
// mode 0: g_vcur = v1 + v2 (logits for pass 3).  mode 1: write v3 to out.
// ============================================================================
__global__ void __launch_bounds__(32)
kf_fin(int mode, float* __restrict__ out) {
    const int bc = blockIdx.x;
    const int b  = bc >> 5;
    const int c  = bc & 31;
    const int t  = threadIdx.x;

    float acc = 0.f;
    if (t < 17) {
        for (int ch = 0; ch < NCHUNK; ch++)
            acc += g_red[(((size_t)c * NCHUNK + ch) * Bn + b) * 17 + t];
    }
    float D = __shfl_sync(0xffffffffu, acc, 16);
    float val = (t < OUTn) ? acc / D : 0.f;
    float sq = val * val;
    #pragma unroll
    for (int off = 16; off; off >>= 1) sq += __shfl_xor_sync(0xffffffffu, sq, off);
    float coef = (sq / (1.f + sq)) * rsqrtf(sq + 1e-8f);
    float v = val * coef;
    if (t < OUTn) {
        if (mode == 0)
            g_vcur[(size_t)bc * OUTn + t] = g_v1[(size_t)bc * OUTn + t] + v;
        else
            out[(size_t)bc * OUTn + t] = v;
    }
}

// ============================================================================
extern "C" void kernel_launch(void* const* d_in, const int* in_sizes, int n_in,
                              void* d_out, int out_size) {
    const float* x = (const float*)d_in[0];           // (64, 4608, 8)
    const float* w = (const float*)d_in[1];           // (4608, 32, 8, 16)
    float* out = (float*)d_out;                       // (64, 32, 16)

    dim3 gp(Cn, NCHUNK);
    k0_transpose<<<dim3(Rn * 2 / 32, Bn / 32), dim3(32, 8)>>>((const float4*)x);
    kpass<<<gp, 256>>>(0, w);          // iteration 1 (e = 1, pure mma)
    kf_v1<<<Bn * Cn, 32>>>();
    kpass<<<gp, 256>>>(1, w);          // iteration 2
    kf_fin<<<Bn * Cn, 32>>>(0, out);
    kpass<<<gp, 256>>>(1, w);          // iteration 3
    kf_fin<<<Bn * Cn, 32>>>(1, out);
}

// round 16
// speedup vs baseline: 1.3838x; 1.3838x over previous
#include <cuda_runtime.h>
#include <cuda_fp16.h>

// Problem constants
#define Bn   64
#define Rn   4608
#define Cn   32
#define INn  8
#define OUTn 16
#define RCHUNK 64
#define NCHUNK 72    // Rn / RCHUNK

// Scratch (device globals; allocation-free per harness rules)
// xA: A-operand pre-formatted in mma fragment order, tf32-rounded.
// xA[((r*4)+mi)*32 + lane] = {a0,a1,a2,a3} for that (r, m-tile, lane).
static __device__ uint4 g_xA[(size_t)Rn * 4 * 32];                  // 9.4 MB, L2-hot
static __device__ float g_red[(size_t)Cn * NCHUNK * Bn * 17];       // pass partials (n[16], d)
static __device__ float g_v1[(size_t)Bn * Cn * OUTn];
static __device__ float g_vcur[(size_t)Bn * Cn * OUTn];             // current logit vector

// ---- tf32 / mma helpers (fragment mapping validated R14/R15) ----
__device__ __forceinline__ unsigned tf32(float f) {
    unsigned r;
    asm("cvt.rna.tf32.f32 %0, %1;" : "=r"(r) : "f"(f));
    return r;
}

__device__ __forceinline__ void mma8_zero(
    float& d0, float& d1, float& d2, float& d3,
    unsigned a0, unsigned a1, unsigned a2, unsigned a3,
    unsigned b0, unsigned b1)
{
    float z = 0.f;
    asm("mma.sync.aligned.m16n8k8.row.col.f32.tf32.tf32.f32 "
        "{%0,%1,%2,%3},{%4,%5,%6,%7},{%8,%9},{%10,%10,%10,%10};"
        : "=f"(d0), "=f"(d1), "=f"(d2), "=f"(d3)
        : "r"(a0), "r"(a1), "r"(a2), "r"(a3), "r"(b0), "r"(b1), "f"(z));
}

__device__ __forceinline__ void mma8_acc(
    float& d0, float& d1, float& d2, float& d3,
    unsigned a0, unsigned a1, unsigned a2, unsigned a3,
    unsigned b0, unsigned b1)
{
    asm("mma.sync.aligned.m16n8k8.row.col.f32.tf32.tf32.f32 "
        "{%0,%1,%2,%3},{%4,%5,%6,%7},{%8,%9},{%0,%1,%2,%3};"
        : "+f"(d0), "+f"(d1), "+f"(d2), "+f"(d3)
        : "r"(a0), "r"(a1), "r"(a2), "r"(a3), "r"(b0), "r"(b1));
}

// ============================================================================
// k0_frag: pre-format x into A-fragment order (tf32-rounded uint4).
// Grid Rn/8 blocks x 256 threads; warp w handles r = blockIdx.x*8 + w.
// Scatter reads are one-time; blocks cover 8 consecutive r so x cache lines
// (which span 4 r) are L1-reused. Stores are fully coalesced LDG.128 food.
// ============================================================================
__global__ void __launch_bounds__(256)
k0_frag(const float* __restrict__ x) {
    const int warp = threadIdx.x >> 5;
    const int lane = threadIdx.x & 31;
    const int r    = blockIdx.x * 8 + warp;
    const int g    = lane >> 2;
    const int t4   = lane & 3;

    #pragma unroll
    for (int mi = 0; mi < 4; mi++) {
        int b0 = mi * 16 + g;
        int b1 = b0 + 8;
        uint4 o;
        o.x = tf32(x[((size_t)b0 * Rn + r) * INn + t4]);
        o.y = tf32(x[((size_t)b1 * Rn + r) * INn + t4]);
        o.z = tf32(x[((size_t)b0 * Rn + r) * INn + t4 + 4]);
        o.w = tf32(x[((size_t)b1 * Rn + r) * INn + t4 + 4]);
        g_xA[((size_t)r * 4 + mi) * 32 + lane] = o;
    }
}

// ============================================================================
// kpass: ONE fused routing pass — u recomputed via tf32 mma, NEVER stored.
// Grid (Cn, NCHUNK), block 256 = 8 warps; warp covers 8 r.
// A: 4 coalesced LDG.128 per warp-r (fragment-order, pre-tf32).
// B: staged into smem in fragment order -> 2 conflict-free LDS.64 per warp-r.
// mode 0: e = 1 -> pure accumulating mma. mode 1: full softmax pass
// (logits -> deduped exp -> regenerate u -> e*u accumulation). R15-validated.
// ============================================================================
__global__ void __launch_bounds__(256)
kpass(int mode, const float* __restrict__ w) {
    const int c     = blockIdx.x;
    const int chunk = blockIdx.y;
    const int r0    = chunk * RCHUNK;
    const int tid   = threadIdx.x;
    const int warp  = tid >> 5;
    const int lane  = tid & 31;
    const int g     = lane >> 2;       // groupID 0..7
    const int t4    = lane & 3;        // thread-in-group 0..3

    __shared__ float sB[RCHUNK * 2 * 32 * 2];  // 32 KB: B frags [rr][ni][lane][frag]; reused for reduction
    __shared__ float sV[Bn * 18];              // padded v
    __shared__ float sD[8][Bn];                // per-warp d partials

    // Stage W chunk -> fragment-order smem (tf32-rounded once).
    // Element [rr][i][o] -> sB[((rr*2 + (o>>3))*32 + (o&7)*4 + (i&3))*2 + (i>>2)]
    {
        const float4* wg = reinterpret_cast<const float4*>(w);
        for (int t = tid; t < RCHUNK * 32; t += 256) {
            int rr = t >> 5;
            int q  = t & 31;
            float4 v = wg[((size_t)(r0 + rr) * Cn + c) * 32 + q];
            float vv[4] = {v.x, v.y, v.z, v.w};
            #pragma unroll
            for (int e = 0; e < 4; e++) {
                int idx = 4 * q + e;
                int i = idx >> 4, o = idx & 15;
                int ln = (o & 7) * 4 + (i & 3);
                sB[(((size_t)rr * 2 + (o >> 3)) * 32 + ln) * 2 + (i >> 2)] =
                    __uint_as_float(tf32(vv[e]));
            }
        }
    }
    if (mode) {
        for (int t = tid; t < Bn * OUTn; t += 256) {
            int b_ = t >> 4, o_ = t & 15;
            sV[b_ * 18 + o_] = g_vcur[((size_t)b_ * Cn + c) * OUTn + o_];
        }
    }
    __syncthreads();

    float dacc[4][2][4];               // n accumulators (mma fragment layout)
    #pragma unroll
    for (int mi = 0; mi < 4; mi++)
        #pragma unroll
        for (int ni = 0; ni < 2; ni++)
            #pragma unroll
            for (int q = 0; q < 4; q++) dacc[mi][ni][q] = 0.f;
    float dsum[8];
    #pragma unroll
    for (int j = 0; j < 8; j++) dsum[j] = 0.f;

    for (int k = 0; k < 8; k++) {
        const int rr = warp * 8 + k;
        const int r  = r0 + rr;

        // A fragments: 4 dense LDG.128 (pre-tf32 bits)
        unsigned A[4][4];
        #pragma unroll
        for (int mi = 0; mi < 4; mi++) {
            uint4 a = g_xA[((size_t)r * 4 + mi) * 32 + lane];
            A[mi][0] = a.x; A[mi][1] = a.y; A[mi][2] = a.z; A[mi][3] = a.w;
        }
        // B fragments: 2 conflict-free LDS.64
        unsigned B[2][2];
        #pragma unroll
        for (int ni = 0; ni < 2; ni++) {
            float2 bf = *reinterpret_cast<const float2*>(
                &sB[(((size_t)rr * 2 + ni) * 32 + lane) * 2]);
            B[ni][0] = __float_as_uint(bf.x);
            B[ni][1] = __float_as_uint(bf.y);
        }

        if (mode == 0) {
            #pragma unroll
            for (int mi = 0; mi < 4; mi++)
                #pragma unroll
                for (int ni = 0; ni < 2; ni++)
                    mma8_acc(dacc[mi][ni][0], dacc[mi][ni][1],
                             dacc[mi][ni][2], dacc[mi][ni][3],
                             A[mi][0], A[mi][1], A[mi][2], A[mi][3],
                             B[ni][0], B[ni][1]);
        } else {
            // Phase A: u -> logit partials (u transient)
            float pb[8];
            #pragma unroll
            for (int j = 0; j < 8; j++) pb[j] = 0.f;
            #pragma unroll
            for (int mi = 0; mi < 4; mi++) {
                int bb = mi * 16 + g;
                #pragma unroll
                for (int ni = 0; ni < 2; ni++) {
                    float u0, u1, u2, u3;
                    mma8_zero(u0, u1, u2, u3,
                              A[mi][0], A[mi][1], A[mi][2], A[mi][3],
                              B[ni][0], B[ni][1]);
                    int o = ni * 8 + 2 * t4;
                    float2 vb  = *reinterpret_cast<const float2*>(&sV[bb * 18 + o]);
                    float2 vb8 = *reinterpret_cast<const float2*>(&sV[(bb + 8) * 18 + o]);
                    pb[2 * mi]     = fmaf(u0, vb.x,  fmaf(u1, vb.y,  pb[2 * mi]));
                    pb[2 * mi + 1] = fmaf(u2, vb8.x, fmaf(u3, vb8.y, pb[2 * mi + 1]));
                }
            }
            // Phase B: reduce over t4, deduped exp + broadcast
            #pragma unroll
            for (int j = 0; j < 8; j++) {
                pb[j] += __shfl_xor_sync(0xffffffffu, pb[j], 1);
                pb[j] += __shfl_xor_sync(0xffffffffu, pb[j], 2);
            }
            float e0 = __expf(pb[2 * t4]);       // logits bounded; no max-sub
            float e1 = __expf(pb[2 * t4 + 1]);
            float e[8];
            #pragma unroll
            for (int j = 0; j < 8; j++)
                e[j] = __shfl_sync(0xffffffffu, (j & 1) ? e1 : e0,
                                   (lane & ~3) | (j >> 1));
            // Phase C: regenerate u, accumulate e*u and d
            #pragma unroll
            for (int mi = 0; mi < 4; mi++) {
                #pragma unroll
                for (int ni = 0; ni < 2; ni++) {
                    float u0, u1, u2, u3;
                    mma8_zero(u0, u1, u2, u3,
                              A[mi][0], A[mi][1], A[mi][2], A[mi][3],
                              B[ni][0], B[ni][1]);
                    dacc[mi][ni][0] = fmaf(e[2 * mi],     u0, dacc[mi][ni][0]);
                    dacc[mi][ni][1] = fmaf(e[2 * mi],     u1, dacc[mi][ni][1]);
                    dacc[mi][ni][2] = fmaf(e[2 * mi + 1], u2, dacc[mi][ni][2]);
                    dacc[mi][ni][3] = fmaf(e[2 * mi + 1], u3, dacc[mi][ni][3]);
                }
            }
            #pragma unroll
            for (int j = 0; j < 8; j++) dsum[j] += e[j];
        }
    }

    // ---- reduce (n, d) across the 8 warps (fixed order) ----
    __syncthreads();                    // done with sB contents
    float* sred = sB;                   // [8 warp][64 b][16 o] = 32 KB exactly
    #pragma unroll
    for (int mi = 0; mi < 4; mi++) {
        #pragma unroll
        for (int ni = 0; ni < 2; ni++) {
            int bb = mi * 16 + g;
            int oo = ni * 8 + 2 * t4;
            float* p = sred + ((size_t)warp * Bn + bb) * OUTn + oo;
            p[0]   = dacc[mi][ni][0];
            p[1]   = dacc[mi][ni][1];
            p[128] = dacc[mi][ni][2];   // b+8 -> +8*16 floats
            p[129] = dacc[mi][ni][3];
        }
    }
    if (t4 == 0) {
        #pragma unroll
        for (int j = 0; j < 8; j++)
            sD[warp][(j >> 1) * 16 + (j & 1) * 8 + g] = dsum[j];
    }
    __syncthreads();
    #pragma unroll
    for (int s = 0; s < 4; s++) {
        int idx = tid * 4 + s;
        int b_ = idx >> 4, o_ = idx & 15;
        float acc = 0.f;
        #pragma unroll
        for (int wg_ = 0; wg_ < 8; wg_++)
            acc += sred[((size_t)wg_ * Bn + b_) * OUTn + o_];
        g_red[(((size_t)c * NCHUNK + chunk) * Bn + b_) * 17 + o_] = acc;
    }
    if (tid < Bn) {
        float acc = 0.f;
        #pragma unroll
        for (int wg_ = 0; wg_ < 8; wg_++) acc += sD[wg_][tid];
        g_red[(((size_t)c * NCHUNK + chunk) * Bn + tid) * 17 + 16] = acc;
    }
}

// ============================================================================
// kf_v1: v1 = squash(mean_r u_r) from pass-0 partials; seeds g_vcur = v1.
// ============================================================================
__global__ void __launch_bounds__(32)
kf_v1() {
    const int bc = blockIdx.x;
    const int b  = bc >> 5;
    const int c  = bc & 31;
    const int t  = threadIdx.x;

    float acc = 0.f;
    if (t < OUTn) {
        for (int ch = 0; ch < NCHUNK; ch++)
            acc += g_red[(((size_t)c * NCHUNK + ch) * Bn + b) * 17 + t];
    }
    float val = (t < OUTn) ? acc * (1.0f / Rn) : 0.f;
    float sq = val * val;
    #pragma unroll
    for (int off = 16; off; off >>= 1) sq += __shfl_xor_sync(0xffffffffu, sq, off);
    float coef = (sq / (1.f + sq)) * rsqrtf(sq + 1e-8f);
    float v = val * coef;
    if (t < OUTn) {
        g_v1[(size_t)bc * OUTn + t]   = v;
        g_vcur[(size_t)bc * OUTn + t] = v;
    }
}

// ============================================================================
// kf_fin: reduce chunk partials -> softmax-weighted sum -> squash.
// mode 0: g_vcur = v1 + v2 (logits for pass 3).  mode 1: write v3 to out.
// ============================================================================
__global__ void __launch_bounds__(32)
kf_fin(int mode, float* __restrict__ out) {
    const int bc = blockIdx.x;
    const int b  = bc >> 5;
    const int c  = bc & 31;
    const int t  = threadIdx.x;

    float acc = 0.f;
    if (t < 17) {
        for (int ch = 0; ch < NCHUNK; ch++)
            acc += g_red[(((size_t)c * NCHUNK + ch) * Bn + b) * 17 + t];
    }
    float D = __shfl_sync(0xffffffffu, acc, 16);
    float val = (t < OUTn) ? acc / D : 0.f;
    float sq = val * val;
    #pragma unroll
    for (int off = 16; off; off >>= 1) sq += __shfl_xor_sync(0xffffffffu, sq, off);
    float coef = (sq / (1.f + sq)) * rsqrtf(sq + 1e-8f);
    float v = val * coef;
    if (t < OUTn) {
        if (mode == 0)
            g_vcur[(size_t)bc * OUTn + t] = g_v1[(size_t)bc * OUTn + t] + v;
        else
            out[(size_t)bc * OUTn + t] = v;
    }
}

// ============================================================================
extern "C" void kernel_launch(void* const* d_in, const int* in_sizes, int n_in,
                              void* d_out, int out_size) {
    const float* x = (const float*)d_in[0];           // (64, 4608, 8)
    const float* w = (const float*)d_in[1];           // (4608, 32, 8, 16)
    float* out = (float*)d_out;                       // (64, 32, 16)

    dim3 gp(Cn, NCHUNK);
    k0_frag<<<Rn / 8, 256>>>(x);
    kpass<<<gp, 256>>>(0, w);          // iteration 1 (e = 1, pure mma)
    kf_v1<<<Bn * Cn, 32>>>();
    kpass<<<gp, 256>>>(1, w);          // iteration 2
    kf_fin<<<Bn * Cn, 32>>>(0, out);
    kpass<<<gp, 256>>>(1, w);          // iteration 3
    kf_fin<<<Bn * Cn, 32>>>(1, out);
}

// round 17
// speedup vs baseline: 1.5859x; 1.1460x over previous
#include <cuda_runtime.h>
#include <cuda_fp16.h>

// Problem constants
#define Bn   64
#define Rn   4608
#define Cn   32
#define INn  8
#define OUTn 16
#define RCHUNK 64
#define NCHUNK 72    // Rn / RCHUNK
#define RPASS  256
#define NSPLIT 18    // Rn / RPASS

// Scratch (device globals; allocation-free per harness rules)
// u_hat layout: [c][r][h(2)][b(64)] of uint4 (8 fp16) -> dense 512B warp accesses
static __device__ uint4 g_uhat4[(size_t)Cn * Rn * 2 * Bn];          // 302 MB
static __device__ uint4 g_xA[(size_t)Rn * 4 * 32];                  // A-frags, tf32 bits (9.4 MB)
static __device__ float g_part[(size_t)Cn * NCHUNK * Bn * OUTn];    // iter-1 partial sums
static __device__ float g_red[(size_t)Cn * NSPLIT * Bn * 17];       // pass partials (n[16], d)
static __device__ float g_v1[(size_t)Bn * Cn * OUTn];
static __device__ float g_vcur[(size_t)Bn * Cn * OUTn];             // current logit vector

// ---- tf32 / mma helpers (fragment mapping validated R14/R15/R16) ----
__device__ __forceinline__ unsigned tf32(float f) {
    unsigned r;
    asm("cvt.rna.tf32.f32 %0, %1;" : "=r"(r) : "f"(f));
    return r;
}

__device__ __forceinline__ void mma8_zero(
    float& d0, float& d1, float& d2, float& d3,
    unsigned a0, unsigned a1, unsigned a2, unsigned a3,
    unsigned b0, unsigned b1)
{
    float z = 0.f;
    asm("mma.sync.aligned.m16n8k8.row.col.f32.tf32.tf32.f32 "
        "{%0,%1,%2,%3},{%4,%5,%6,%7},{%8,%9},{%10,%10,%10,%10};"
        : "=f"(d0), "=f"(d1), "=f"(d2), "=f"(d3)
        : "r"(a0), "r"(a1), "r"(a2), "r"(a3), "r"(b0), "r"(b1), "f"(z));
}

__device__ __forceinline__ void mma8_acc(
    float& d0, float& d1, float& d2, float& d3,
    unsigned a0, unsigned a1, unsigned a2, unsigned a3,
    unsigned b0, unsigned b1)
{
    asm("mma.sync.aligned.m16n8k8.row.col.f32.tf32.tf32.f32 "
        "{%0,%1,%2,%3},{%4,%5,%6,%7},{%8,%9},{%0,%1,%2,%3};"
        : "+f"(d0), "+f"(d1), "+f"(d2), "+f"(d3)
        : "r"(a0), "r"(a1), "r"(a2), "r"(a3), "r"(b0), "r"(b1));
}

// ============================================================================
// k0_frag: pre-format x into A-fragment order (tf32-rounded uint4).
// ============================================================================
__global__ void __launch_bounds__(256)
k0_frag(const float* __restrict__ x) {
    const int warp = threadIdx.x >> 5;
    const int lane = threadIdx.x & 31;
    const int r    = blockIdx.x * 8 + warp;
    const int g    = lane >> 2;
    const int t4   = lane & 3;

    #pragma unroll
    for (int mi = 0; mi < 4; mi++) {
        int b0 = mi * 16 + g;
        int b1 = b0 + 8;
        uint4 o;
        o.x = tf32(x[((size_t)b0 * Rn + r) * INn + t4]);
        o.y = tf32(x[((size_t)b1 * Rn + r) * INn + t4]);
        o.z = tf32(x[((size_t)b0 * Rn + r) * INn + t4 + 4]);
        o.w = tf32(x[((size_t)b1 * Rn + r) * INn + t4 + 4]);
        g_xA[((size_t)r * 4 + mi) * 32 + lane] = o;
    }
}

// ============================================================================
// k1 (2-c-BLOCKED tensor): u_hat fp16 + iter-1 partials for TWO capsules per
// CTA. Grid (Cn/2, NCHUNK); block 256 = 8 warps; warp covers 8 r.
// One set of A fragment loads (4 LDG.128/warp-r) feeds both c's mma work ->
// x L2-traffic and load-latency exposure per unit work halved vs R14.
// B staged per c in fragment order (2 conflict-free LDS.64 per c per r).
// ============================================================================
__global__ void __launch_bounds__(256, 2)
k1_uhat(const float* __restrict__ w) {
    const int cg    = blockIdx.x;          // capsule pair: c0 = 2cg, c1 = 2cg+1
    const int chunk = blockIdx.y;
    const int r0    = chunk * RCHUNK;
    const int tid   = threadIdx.x;
    const int warp  = tid >> 5;
    const int lane  = tid & 31;
    const int g     = lane >> 2;
    const int t4    = lane & 3;

    __shared__ float sB[2][RCHUNK * 2 * 32 * 2];   // 64 KB: B frags per c; reused for reduction

    // Stage W for both c in fragment order (tf32-rounded once).
    {
        const float4* wg = reinterpret_cast<const float4*>(w);
        for (int t = tid; t < 2 * RCHUNK * 32; t += 256) {
            int cc = t >= RCHUNK * 32;
            int tt = t - cc * RCHUNK * 32;
            int rr = tt >> 5;
            int q  = tt & 31;
            float4 v = wg[((size_t)(r0 + rr) * Cn + (2 * cg + cc)) * 32 + q];
            float vv[4] = {v.x, v.y, v.z, v.w};
            #pragma unroll
            for (int e = 0; e < 4; e++) {
                int idx = 4 * q + e;
                int i = idx >> 4, o = idx & 15;
                int ln = (o & 7) * 4 + (i & 3);
                sB[cc][(((size_t)rr * 2 + (o >> 3)) * 32 + ln) * 2 + (i >> 2)] =
                    __uint_as_float(tf32(vv[e]));
            }
        }
    }
    __syncthreads();

    float dacc[2][4][2][4];            // iter-1 accumulators, both c
    #pragma unroll
    for (int cc = 0; cc < 2; cc++)
        #pragma unroll
        for (int mi = 0; mi < 4; mi++)
            #pragma unroll
            for (int ni = 0; ni < 2; ni++)
                #pragma unroll
                for (int q = 0; q < 4; q++) dacc[cc][mi][ni][q] = 0.f;

    __half2* gu2 = reinterpret_cast<__half2*>(g_uhat4);

    for (int k = 0; k < 8; k++) {
        const int rr = warp * 8 + k;
        const int r  = r0 + rr;

        // A fragments: 4 dense LDG.128 — loaded ONCE, reused for both c
        unsigned A[4][4];
        #pragma unroll
        for (int mi = 0; mi < 4; mi++) {
            uint4 a = g_xA[((size_t)r * 4 + mi) * 32 + lane];
            A[mi][0] = a.x; A[mi][1] = a.y; A[mi][2] = a.z; A[mi][3] = a.w;
        }

        #pragma unroll
        for (int cc = 0; cc < 2; cc++) {
            const int c = 2 * cg + cc;
            // B fragments: 2 conflict-free LDS.64
            unsigned B[2][2];
            #pragma unroll
            for (int ni = 0; ni < 2; ni++) {
                float2 bf = *reinterpret_cast<const float2*>(
                    &sB[cc][(((size_t)rr * 2 + ni) * 32 + lane) * 2]);
                B[ni][0] = __float_as_uint(bf.x);
                B[ni][1] = __float_as_uint(bf.y);
            }
            #pragma unroll
            for (int mi = 0; mi < 4; mi++) {
                #pragma unroll
                for (int ni = 0; ni < 2; ni++) {
                    float d0, d1, d2, d3;
                    mma8_zero(d0, d1, d2, d3,
                              A[mi][0], A[mi][1], A[mi][2], A[mi][3],
                              B[ni][0], B[ni][1]);
                    mma8_acc(dacc[cc][mi][ni][0], dacc[cc][mi][ni][1],
                             dacc[cc][mi][ni][2], dacc[cc][mi][ni][3],
                             A[mi][0], A[mi][1], A[mi][2], A[mi][3],
                             B[ni][0], B[ni][1]);
                    int bb = mi * 16 + g;
                    size_t h2 = ((size_t)(c * Rn + r) * 2 + ni) * 256 + bb * 4 + t4;
                    gu2[h2]      = __floats2half2_rn(d0, d1);
                    gu2[h2 + 32] = __floats2half2_rn(d2, d3);   // b+8
                }
            }
        }
    }

    // ---- reduce iter-1 partials across the 8 warps, both c (fixed order) ----
    __syncthreads();                    // done with sB contents
    #pragma unroll
    for (int cc = 0; cc < 2; cc++) {
        float* sred = sB[cc];           // [8 warp][64 b][16 o] = 32 KB each
        #pragma unroll
        for (int mi = 0; mi < 4; mi++) {
            #pragma unroll
            for (int ni = 0; ni < 2; ni++) {
                int bb = mi * 16 + g;
                int oo = ni * 8 + 2 * t4;
                float* p = sred + ((size_t)warp * Bn + bb) * OUTn + oo;
                p[0]   = dacc[cc][mi][ni][0];
                p[1]   = dacc[cc][mi][ni][1];
                p[128] = dacc[cc][mi][ni][2];
                p[129] = dacc[cc][mi][ni][3];
            }
        }
    }
    __syncthreads();
    #pragma unroll
    for (int s = 0; s < 8; s++) {
        int idx = tid * 8 + s;              // 2048 (cc, b, o) slots
        int cc = idx >> 10;
        int rem = idx & 1023;
        int b_ = rem >> 4, o_ = rem & 15;
        float acc = 0.f;
        #pragma unroll
        for (int wg_ = 0; wg_ < 8; wg_++)
            acc += sB[cc][((size_t)wg_ * Bn + b_) * OUTn + o_];
        g_part[(((size_t)(2 * cg + cc) * NCHUNK + chunk) * Bn + b_) * OUTn + o_] = acc;
    }
}

// ============================================================================
// kf_v1: v1 = squash(mean_r u_r) per (b,c); seeds g_vcur = v1.
// ============================================================================
__global__ void __launch_bounds__(32)
kf_v1() {
    const int bc = blockIdx.x;
    const int b  = bc >> 5;
    const int c  = bc & 31;
    const int t  = threadIdx.x;

    float acc = 0.f;
    if (t < OUTn) {
        for (int ch = 0; ch < NCHUNK; ch++)
            acc += g_part[(((size_t)c * NCHUNK + ch) * Bn + b) * OUTn + t];
    }
    float val = (t < OUTn) ? acc * (1.0f / Rn) : 0.f;
    float sq = val * val;
    #pragma unroll
    for (int off = 16; off; off >>= 1) sq += __shfl_xor_sync(0xffffffffu, sq, off);
    float coef = (sq / (1.f + sq)) * rsqrtf(sq + 1e-8f);
    float v = val * coef;
    if (t < OUTn) {
        g_v1[(size_t)bc * OUTn + t]   = v;
        g_vcur[(size_t)bc * OUTn + t] = v;
    }
}

// ============================================================================
// k2p (exact R12 body, measured 51.9us / DRAM 74.4%): streaming routing
// pass, o-split across lane pairs, single-wave grid (Cn, 18).
// ============================================================================
__global__ void __launch_bounds__(256)
k2p() {
    const int c     = blockIdx.x;
    const int split = blockIdx.y;           // 0..17, 256 r each
    const int tid   = threadIdx.x;
    const int warp  = tid >> 5;
    const int lane  = tid & 31;
    const int rg    = warp >> 2;            // 0..1 (128 r each)
    const int bq    = warp & 3;             // 0..3
    const int hh    = lane >> 4;            // 0/1 (which 8 outputs)
    const int b     = bq * 16 + (lane & 15);

    __shared__ float sV[Bn * OUTn];
    __shared__ float sRed[2][Bn][18];

    for (int t = tid; t < Bn * OUTn; t += 256) {
        int b_ = t >> 4, o_ = t & 15;
        sV[t] = g_vcur[((size_t)b_ * Cn + c) * OUTn + o_];
    }
    __syncthreads();

    float v[8];
    #pragma unroll
    for (int j = 0; j < 8; j++) v[j] = sV[b * OUTn + hh * 8 + j];

    float d = 0.f;
    float n[8];
    #pragma unroll
    for (int j = 0; j < 8; j++) n[j] = 0.f;

    const int rbase = split * RPASS + rg * 128;
    size_t base = ((size_t)(c * Rn + rbase) * 2 + hh) * Bn + b;

    #pragma unroll 8
    for (int k = 0; k < 128; k++) {
        uint4 q = g_uhat4[base + (size_t)k * 2 * Bn];
        union { __half2 h[4]; uint4 q4; } cv;
        cv.q4 = q;
        float u[8];
        #pragma unroll
        for (int j = 0; j < 4; j++) {
            float2 f = __half22float2(cv.h[j]);
            u[2 * j]     = f.x;
            u[2 * j + 1] = f.y;
        }
        float t = 0.f;
        #pragma unroll
        for (int j = 0; j < 8; j++) t = fmaf(u[j], v[j], t);
        t += __shfl_xor_sync(0xffffffffu, t, 16);       // full 16-dim dot
        float e = __expf(t);
        d += e;
        #pragma unroll
        for (int j = 0; j < 8; j++) n[j] = fmaf(e, u[j], n[j]);
    }

    #pragma unroll
    for (int j = 0; j < 8; j++) sRed[rg][b][hh * 8 + j] = n[j];
    if (hh == 0) sRed[rg][b][16] = d;
    __syncthreads();

    for (int t = tid; t < Bn * 17; t += 256) {
        int b_ = t / 17, o_ = t % 17;
        g_red[(((size_t)c * NSPLIT + split) * Bn + b_) * 17 + o_] =
            sRed[0][b_][o_] + sRed[1][b_][o_];
    }
}

// ============================================================================
// kf_fin: reduce slab partials -> softmax-weighted sum -> squash.
// mode 0: g_vcur = v1 + v2.  mode 1: write v3 to out.
// ============================================================================
__global__ void __launch_bounds__(32)
kf_fin(int mode, float* __restrict__ out) {
    const int bc = blockIdx.x;
    const int b  = bc >> 5;
    const int c  = bc & 31;
    const int t  = threadIdx.x;

    float acc = 0.f;
    if (t < 17) {
        for (int s = 0; s < NSPLIT; s++)
            acc += g_red[(((size_t)c * NSPLIT + s) * Bn + b) * 17 + t];
    }
    float D = __shfl_sync(0xffffffffu, acc, 16);
    float val = (t < OUTn) ? acc / D : 0.f;
    float sq = val * val;
    #pragma unroll
    for (int off = 16; off; off >>= 1) sq += __shfl_xor_sync(0xffffffffu, sq, off);
    float coef = (sq / (1.f + sq)) * rsqrtf(sq + 1e-8f);
    float v = val * coef;
    if (t < OUTn) {
        if (mode == 0)
            g_vcur[(size_t)bc * OUTn + t] = g_v1[(size_t)bc * OUTn + t] + v;
        else
            out[(size_t)bc * OUTn + t] = v;
    }
}

// ============================================================================
extern "C" void kernel_launch(void* const* d_in, const int* in_sizes, int n_in,
                              void* d_out, int out_size) {
    const float* x = (const float*)d_in[0];           // (64, 4608, 8)
    const float* w = (const float*)d_in[1];           // (4608, 32, 8, 16)
    float* out = (float*)d_out;                       // (64, 32, 16)

    k0_frag<<<Rn / 8, 256>>>(x);
    k1_uhat<<<dim3(Cn / 2, NCHUNK), 256>>>(w);
    kf_v1<<<Bn * Cn, 32>>>();
    k2p<<<dim3(Cn, NSPLIT), 256>>>();
    kf_fin<<<Bn * Cn, 32>>>(0, out);
    k2p<<<dim3(Cn, NSPLIT), 256>>>();
    kf_fin<<<Bn * Cn, 32>>>(1, out);
}